// round 3
// baseline (speedup 1.0000x reference)
#include <cuda_runtime.h>
#include <cstdint>

// Problem constants
#define NWIN  4096
#define NTOK  64
#define DIM   192
#define HEADS 6
#define QK_SCALE 0.17677669529663687f   // 32^-0.5

#define NTHREADS 512

// smem layout (floats)
#define CPAD 196
#define XPAD 68
#define OFF_XB 0                          // [64][68] A big (tf32 bits)
#define OFF_XS (OFF_XB + NTOK*XPAD)       // [64][68] A small
#define OFF_SQ (OFF_XS + NTOK*XPAD)       // [64][196] Q (scaled) -> later O in-place
#define OFF_SK (OFF_SQ + NTOK*CPAD)
#define OFF_SV (OFF_SK + NTOK*CPAD)
#define SMEM_FLOATS (OFF_SV + NTOK*CPAD)  // 46336 floats = 185344 bytes

__device__ float  g_bias[HEADS * NTOK * NTOK];
__device__ float4 g_wqkv[24 * 72 * 32];   // [kstep][ntile][lane] = {b0big,b0small,b1big,b1small}
__device__ float4 g_wproj[24 * 24 * 32];

__device__ __forceinline__ uint32_t tf32_round(float v) {
    uint32_t u; asm("cvt.rna.tf32.f32 %0, %1;" : "=r"(u) : "f"(v)); return u;
}

#define MMA_TF32(C, A0, A1, A2, A3, B0, B1)                                          \
    asm("mma.sync.aligned.m16n8k8.row.col.f32.tf32.tf32.f32 "                        \
        "{%0,%1,%2,%3},{%4,%5,%6,%7},{%8,%9},{%0,%1,%2,%3};"                         \
        : "+f"((C)[0]), "+f"((C)[1]), "+f"((C)[2]), "+f"((C)[3])                     \
        : "r"(A0), "r"(A1), "r"(A2), "r"(A3), "r"(B0), "r"(B1))

__global__ void bias_expand_kernel(const float* __restrict__ bias_table,
                                   const int* __restrict__ rel_index) {
    int e = blockIdx.x * blockDim.x + threadIdx.x;
    if (e >= HEADS * NTOK * NTOK) return;
    int h  = e / (NTOK * NTOK);
    int ij = e % (NTOK * NTOK);
    g_bias[e] = bias_table[rel_index[ij] * HEADS + h];
}

__global__ void pack_weights_kernel(const float* __restrict__ qkv_w,
                                    const float* __restrict__ proj_w) {
    const int NQ = 24 * 72 * 32;
    const int NP = 24 * 24 * 32;
    int idx = blockIdx.x * blockDim.x + threadIdx.x;
    if (idx < NQ) {
        int lane = idx & 31, nt = (idx >> 5) % 72, ks = idx / (72 * 32);
        int n = nt * 8 + (lane >> 2), k = ks * 8 + (lane & 3);
        float w0 = qkv_w[n * DIM + k], w1 = qkv_w[n * DIM + k + 4];
        uint32_t b0 = tf32_round(w0), b1 = tf32_round(w1);
        uint32_t s0 = tf32_round(w0 - __uint_as_float(b0));
        uint32_t s1 = tf32_round(w1 - __uint_as_float(b1));
        g_wqkv[idx] = make_float4(__uint_as_float(b0), __uint_as_float(s0),
                                  __uint_as_float(b1), __uint_as_float(s1));
    } else if (idx < NQ + NP) {
        int j = idx - NQ;
        int lane = j & 31, nt = (j >> 5) % 24, ks = j / (24 * 32);
        int n = nt * 8 + (lane >> 2), k = ks * 8 + (lane & 3);
        float w0 = proj_w[n * DIM + k], w1 = proj_w[n * DIM + k + 4];
        uint32_t b0 = tf32_round(w0), b1 = tf32_round(w1);
        uint32_t s0 = tf32_round(w0 - __uint_as_float(b0));
        uint32_t s1 = tf32_round(w1 - __uint_as_float(b1));
        g_wproj[j] = make_float4(__uint_as_float(b0), __uint_as_float(s0),
                                 __uint_as_float(b1), __uint_as_float(s1));
    }
}

// Stage a [64 x 64] fp32 chunk into tf32 big/small smem buffers (512 threads -> 2 iters).
#define STAGE_CHUNK(SRC_BASE, SRC_STRIDE, COL0)                                      \
    do {                                                                             \
        _Pragma("unroll")                                                            \
        for (int it = 0; it < 2; ++it) {                                             \
            int idx = tid + NTHREADS * it;                                           \
            int r  = idx >> 4;                                                       \
            int c4 = (idx & 15) * 4;                                                 \
            float4 v = *reinterpret_cast<const float4*>((SRC_BASE) + r * (SRC_STRIDE) + (COL0) + c4); \
            float vv[4] = {v.x, v.y, v.z, v.w};                                      \
            _Pragma("unroll")                                                        \
            for (int jj2 = 0; jj2 < 4; ++jj2) {                                      \
                uint32_t bb = tf32_round(vv[jj2]);                                   \
                uint32_t ss = tf32_round(vv[jj2] - __uint_as_float(bb));             \
                XB[r * XPAD + c4 + jj2] = __uint_as_float(bb);                       \
                XS[r * XPAD + c4 + jj2] = __uint_as_float(ss);                       \
            }                                                                        \
        }                                                                            \
    } while (0)

__global__ __launch_bounds__(NTHREADS, 1)
void msa_fused_kernel(const float* __restrict__ x,
                      const float* __restrict__ qkv_b,
                      const float* __restrict__ proj_b,
                      float* __restrict__ out)
{
    extern __shared__ float sm[];
    float* XB = sm + OFF_XB;
    float* XS = sm + OFF_XS;
    float* SQ = sm + OFF_SQ;   // Q, then O in-place
    float* SK = sm + OFF_SK;
    float* SV = sm + OFF_SV;

    const int tid  = threadIdx.x;
    const int lane = tid & 31;
    const int warp = tid >> 5;     // 0..15
    const int wc   = warp & 7;     // column group
    const int mh   = warp >> 3;    // m-half (rows mh*32 .. mh*32+31)
    const int g    = lane >> 2;    // fragment group id
    const int t    = lane & 3;     // thread-in-group
    const int b    = blockIdx.x;
    const float* xb = x + (size_t)b * (NTOK * DIM);
    float* ob       = out + (size_t)b * (NTOK * DIM);

    // ================= Phase 1: QKV GEMM (3xTF32 mma) =================
    // Warp (mh, wc): rows [32*mh, 32*mh+32) (2 m-tiles), cols [72*wc, 72*wc+72) (9 n-tiles).
    {
        float c[2][9][4];
        #pragma unroll
        for (int mt = 0; mt < 2; ++mt)
            #pragma unroll
            for (int nt = 0; nt < 9; ++nt)
                #pragma unroll
                for (int i = 0; i < 4; ++i) c[mt][nt][i] = 0.f;

        for (int kb = 0; kb < 3; ++kb) {
            __syncthreads();
            STAGE_CHUNK(xb, DIM, kb * 64);
            __syncthreads();
            for (int ks = 0; ks < 8; ++ks) {
                uint32_t ab[2][4], asml[2][4];
                const int cb = ks * 8 + t;
                #pragma unroll
                for (int mt = 0; mt < 2; ++mt) {
                    int r0 = (mh * 32 + mt * 16 + g) * XPAD, r1 = r0 + 8 * XPAD;
                    ab[mt][0]   = __float_as_uint(XB[r0 + cb]);
                    ab[mt][1]   = __float_as_uint(XB[r1 + cb]);
                    ab[mt][2]   = __float_as_uint(XB[r0 + cb + 4]);
                    ab[mt][3]   = __float_as_uint(XB[r1 + cb + 4]);
                    asml[mt][0] = __float_as_uint(XS[r0 + cb]);
                    asml[mt][1] = __float_as_uint(XS[r1 + cb]);
                    asml[mt][2] = __float_as_uint(XS[r0 + cb + 4]);
                    asml[mt][3] = __float_as_uint(XS[r1 + cb + 4]);
                }
                const int ksg = kb * 8 + ks;
                #pragma unroll
                for (int nt = 0; nt < 9; ++nt) {
                    float4 B4 = g_wqkv[(ksg * 72 + wc * 9 + nt) * 32 + lane];
                    uint32_t bb0 = __float_as_uint(B4.x), bs0 = __float_as_uint(B4.y);
                    uint32_t bb1 = __float_as_uint(B4.z), bs1 = __float_as_uint(B4.w);
                    #pragma unroll
                    for (int mt = 0; mt < 2; ++mt) {
                        MMA_TF32(c[mt][nt], ab[mt][0], ab[mt][1], ab[mt][2], ab[mt][3], bb0, bb1);
                        MMA_TF32(c[mt][nt], ab[mt][0], ab[mt][1], ab[mt][2], ab[mt][3], bs0, bs1);
                        MMA_TF32(c[mt][nt], asml[mt][0], asml[mt][1], asml[mt][2], asml[mt][3], bb0, bb1);
                    }
                }
            }
        }
        // Epilogue: + bias, scatter to SQ (scaled) / SK / SV
        #pragma unroll
        for (int nt = 0; nt < 9; ++nt) {
            int colbase = wc * 72 + nt * 8 + 2 * t;
            #pragma unroll
            for (int ii = 0; ii < 2; ++ii) {
                int gcol = colbase + ii;
                float bias = qkv_b[gcol];
                #pragma unroll
                for (int mt = 0; mt < 2; ++mt)
                    #pragma unroll
                    for (int rr = 0; rr < 2; ++rr) {
                        float v = c[mt][nt][rr * 2 + ii] + bias;
                        int row = mh * 32 + mt * 16 + g + 8 * rr;
                        if (gcol < DIM)            SQ[row * CPAD + gcol]            = v * QK_SCALE;
                        else if (gcol < 2 * DIM)   SK[row * CPAD + gcol - DIM]      = v;
                        else                       SV[row * CPAD + gcol - 2 * DIM]  = v;
                    }
            }
        }
    }
    __syncthreads();

    // ================= Phase 2: attention (FFMA), 8 threads per row, O in-place over Q ====
    {
        const int r  = tid >> 3;   // query row 0..63
        const int qq = tid & 7;    // 8 cooperating lanes per row (within a warp)
        for (int h = 0; h < HEADS; ++h) {
            float qreg[32];
            #pragma unroll
            for (int dc = 0; dc < 8; ++dc) {
                float4 v = *reinterpret_cast<const float4*>(&SQ[r * CPAD + h * 32 + dc * 4]);
                qreg[dc * 4 + 0] = v.x; qreg[dc * 4 + 1] = v.y;
                qreg[dc * 4 + 2] = v.z; qreg[dc * 4 + 3] = v.w;
            }
            const float* gb = g_bias + h * (NTOK * NTOK) + r * NTOK;
            float s[8];
            #pragma unroll
            for (int jj = 0; jj < 8; ++jj) {
                int j = jj * 8 + qq;
                float a = 0.f;
                #pragma unroll
                for (int dc = 0; dc < 8; ++dc) {
                    float4 kv = *reinterpret_cast<const float4*>(&SK[j * CPAD + h * 32 + dc * 4]);
                    a += qreg[dc * 4 + 0] * kv.x + qreg[dc * 4 + 1] * kv.y
                       + qreg[dc * 4 + 2] * kv.z + qreg[dc * 4 + 3] * kv.w;
                }
                s[jj] = a + gb[j];
            }
            float m = s[0];
            #pragma unroll
            for (int jj = 1; jj < 8; ++jj) m = fmaxf(m, s[jj]);
            m = fmaxf(m, __shfl_xor_sync(0xffffffffu, m, 1));
            m = fmaxf(m, __shfl_xor_sync(0xffffffffu, m, 2));
            m = fmaxf(m, __shfl_xor_sync(0xffffffffu, m, 4));
            float l = 0.f;
            #pragma unroll
            for (int jj = 0; jj < 8; ++jj) { s[jj] = __expf(s[jj] - m); l += s[jj]; }
            l += __shfl_xor_sync(0xffffffffu, l, 1);
            l += __shfl_xor_sync(0xffffffffu, l, 2);
            l += __shfl_xor_sync(0xffffffffu, l, 4);
            float o[32];
            #pragma unroll
            for (int d = 0; d < 32; ++d) o[d] = 0.f;
            #pragma unroll
            for (int jj = 0; jj < 8; ++jj) {
                int j = jj * 8 + qq;
                float p = s[jj];
                #pragma unroll
                for (int dc = 0; dc < 8; ++dc) {
                    float4 vv = *reinterpret_cast<const float4*>(&SV[j * CPAD + h * 32 + dc * 4]);
                    o[dc * 4 + 0] += p * vv.x; o[dc * 4 + 1] += p * vv.y;
                    o[dc * 4 + 2] += p * vv.z; o[dc * 4 + 3] += p * vv.w;
                }
            }
            #pragma unroll
            for (int d = 0; d < 32; ++d) {
                o[d] += __shfl_xor_sync(0xffffffffu, o[d], 1);
                o[d] += __shfl_xor_sync(0xffffffffu, o[d], 2);
                o[d] += __shfl_xor_sync(0xffffffffu, o[d], 4);
            }
            float linv = 1.f / l;
            #pragma unroll
            for (int u = 0; u < 4; ++u) {
                int d = u * 8 + qq;
                SQ[r * CPAD + h * 32 + d] = o[d] * linv;
            }
        }
    }
    __syncthreads();

    // ================= Phase 3: proj GEMM (3xTF32 mma), A = O (in SQ) =================
    {
        float c[2][3][4];
        #pragma unroll
        for (int mt = 0; mt < 2; ++mt)
            #pragma unroll
            for (int nt = 0; nt < 3; ++nt)
                #pragma unroll
                for (int i = 0; i < 4; ++i) c[mt][nt][i] = 0.f;

        for (int kb = 0; kb < 3; ++kb) {
            __syncthreads();
            STAGE_CHUNK(SQ, CPAD, kb * 64);
            __syncthreads();
            for (int ks = 0; ks < 8; ++ks) {
                uint32_t ab[2][4], asml[2][4];
                const int cb = ks * 8 + t;
                #pragma unroll
                for (int mt = 0; mt < 2; ++mt) {
                    int r0 = (mh * 32 + mt * 16 + g) * XPAD, r1 = r0 + 8 * XPAD;
                    ab[mt][0]   = __float_as_uint(XB[r0 + cb]);
                    ab[mt][1]   = __float_as_uint(XB[r1 + cb]);
                    ab[mt][2]   = __float_as_uint(XB[r0 + cb + 4]);
                    ab[mt][3]   = __float_as_uint(XB[r1 + cb + 4]);
                    asml[mt][0] = __float_as_uint(XS[r0 + cb]);
                    asml[mt][1] = __float_as_uint(XS[r1 + cb]);
                    asml[mt][2] = __float_as_uint(XS[r0 + cb + 4]);
                    asml[mt][3] = __float_as_uint(XS[r1 + cb + 4]);
                }
                const int ksg = kb * 8 + ks;
                #pragma unroll
                for (int nt = 0; nt < 3; ++nt) {
                    float4 B4 = g_wproj[(ksg * 24 + wc * 3 + nt) * 32 + lane];
                    uint32_t bb0 = __float_as_uint(B4.x), bs0 = __float_as_uint(B4.y);
                    uint32_t bb1 = __float_as_uint(B4.z), bs1 = __float_as_uint(B4.w);
                    #pragma unroll
                    for (int mt = 0; mt < 2; ++mt) {
                        MMA_TF32(c[mt][nt], ab[mt][0], ab[mt][1], ab[mt][2], ab[mt][3], bb0, bb1);
                        MMA_TF32(c[mt][nt], ab[mt][0], ab[mt][1], ab[mt][2], ab[mt][3], bs0, bs1);
                        MMA_TF32(c[mt][nt], asml[mt][0], asml[mt][1], asml[mt][2], asml[mt][3], bb0, bb1);
                    }
                }
            }
        }
        // Epilogue: + bias, write to gmem (float2 pairs)
        #pragma unroll
        for (int nt = 0; nt < 3; ++nt) {
            int colbase = wc * 24 + nt * 8 + 2 * t;
            float b0 = proj_b[colbase], b1 = proj_b[colbase + 1];
            #pragma unroll
            for (int mt = 0; mt < 2; ++mt)
                #pragma unroll
                for (int rr = 0; rr < 2; ++rr) {
                    int row = mh * 32 + mt * 16 + g + 8 * rr;
                    float2 v;
                    v.x = c[mt][nt][rr * 2 + 0] + b0;
                    v.y = c[mt][nt][rr * 2 + 1] + b1;
                    *reinterpret_cast<float2*>(ob + row * DIM + colbase) = v;
                }
        }
    }
}

extern "C" void kernel_launch(void* const* d_in, const int* in_sizes, int n_in,
                              void* d_out, int out_size) {
    const float* x          = (const float*)d_in[0];
    const float* qkv_w      = (const float*)d_in[1];
    const float* qkv_b      = (const float*)d_in[2];
    const float* proj_w     = (const float*)d_in[3];
    const float* proj_b     = (const float*)d_in[4];
    const float* bias_table = (const float*)d_in[5];
    const int*   rel_index  = (const int*)d_in[6];
    float* out = (float*)d_out;

    cudaFuncSetAttribute(msa_fused_kernel, cudaFuncAttributeMaxDynamicSharedMemorySize,
                         SMEM_FLOATS * (int)sizeof(float));

    bias_expand_kernel<<<(HEADS * NTOK * NTOK + 255) / 256, 256>>>(bias_table, rel_index);
    pack_weights_kernel<<<(24 * 72 * 32 + 24 * 24 * 32 + 255) / 256, 256>>>(qkv_w, proj_w);
    msa_fused_kernel<<<NWIN, NTHREADS, SMEM_FLOATS * sizeof(float)>>>(x, qkv_b, proj_b, out);
}